// round 2
// baseline (speedup 1.0000x reference)
#include <cuda_runtime.h>
#include <cstdint>
#include <cstddef>

// ---------------- problem constants ----------------
namespace {
constexpr int B    = 8;
constexpr int T    = 4096;
constexpr int NT   = B * T;        // 32768 tokens
constexpr int DIN  = 1176;
constexpr int D    = 1024;
constexpr int E    = 8;
constexpr int BNK  = 64;           // bottleneck
constexpr int L    = 4;
constexpr int OUTD = 4096;
constexpr int CAP  = 32768;        // max tokens per expert bucket
}

// ---------------- device scratch (no runtime allocs allowed) ----------------
__device__ float g_hA[(size_t)NT * D];
__device__ float g_hB[(size_t)NT * D];
__device__ float g_g[B * D];
__device__ float g_skin_probs[B * 3];
__device__ float g_skin_logits[B * 3];
__device__ int   g_counts[E];
__device__ int   g_btok[E * CAP];
__device__ float g_bw[E * CAP];
__device__ float g_aux_probs[B * E];
__device__ float g_aux_mask[B * E];
__device__ float g_aux_total;

// ---------------- in_proj GEMM: g_hA = X(NT x DIN) @ W(DIN x D) ----------------
// 128x128 tile, BK=8, 256 threads, 8x8 micro-tile (strided cols/rows for bank safety)
__global__ __launch_bounds__(256) void inproj_kernel(const float* __restrict__ X,
                                                     const float* __restrict__ W) {
  constexpr int BM = 128, BNt = 128, BK = 8;
  __shared__ float As[BK][BM + 4];
  __shared__ float Bs[BK][BNt];
  int tid = threadIdx.x;
  int tx = tid & 15, ty = tid >> 4;
  int m0 = blockIdx.y * BM, n0 = blockIdx.x * BNt;
  float acc[8][8];
#pragma unroll
  for (int i = 0; i < 8; i++)
#pragma unroll
    for (int j = 0; j < 8; j++) acc[i][j] = 0.f;

  for (int k0 = 0; k0 < DIN; k0 += BK) {  // 1176 = 147 * 8, exact
    {
      int r = tid >> 1;
      int c = (tid & 1) * 4;
      const float* src = X + (size_t)(m0 + r) * DIN + k0 + c;
#pragma unroll
      for (int j = 0; j < 4; j++) As[c + j][r] = src[j];
    }
    {
      int kr0 = tid >> 7;  // 0..1
      int c = tid & 127;
#pragma unroll
      for (int j = 0; j < 4; j++) {
        int kr = kr0 + j * 2;
        Bs[kr][c] = W[(size_t)(k0 + kr) * D + n0 + c];
      }
    }
    __syncthreads();
#pragma unroll
    for (int kk = 0; kk < BK; kk++) {
      float a[8], b[8];
#pragma unroll
      for (int i = 0; i < 8; i++) a[i] = As[kk][ty + 16 * i];
#pragma unroll
      for (int j = 0; j < 8; j++) b[j] = Bs[kk][tx + 16 * j];
#pragma unroll
      for (int i = 0; i < 8; i++)
#pragma unroll
        for (int j = 0; j < 8; j++) acc[i][j] = fmaf(a[i], b[j], acc[i][j]);
    }
    __syncthreads();
  }
#pragma unroll
  for (int i = 0; i < 8; i++) {
    int m = m0 + ty + 16 * i;
    float* dst = g_hA + (size_t)m * D + n0;
#pragma unroll
    for (int j = 0; j < 8; j++) dst[tx + 16 * j] = acc[i][j];
  }
}

// ---------------- per-image mean of g_hA -> g_g ----------------
__global__ void gmean_kernel() {
  int img = blockIdx.x;
  int d = blockIdx.y * 256 + threadIdx.x;
  const float* base = g_hA + (size_t)img * T * D + d;
  float s0 = 0.f, s1 = 0.f, s2 = 0.f, s3 = 0.f;
  for (int t = 0; t < T; t += 4) {
    s0 += base[(size_t)t * D];
    s1 += base[(size_t)(t + 1) * D];
    s2 += base[(size_t)(t + 2) * D];
    s3 += base[(size_t)(t + 3) * D];
  }
  g_g[img * D + d] = (s0 + s1 + s2 + s3) * (1.f / (float)T);
}

// ---------------- skin classifier: logits + softmax probs ----------------
__global__ __launch_bounds__(256) void skin_kernel(const float* __restrict__ w_sc1,
                                                   const float* __restrict__ b_sc1,
                                                   const float* __restrict__ w_sc2,
                                                   const float* __restrict__ b_sc2) {
  __shared__ float s1[B][64];
  __shared__ float lg[B][3];
  int tid = threadIdx.x;
  for (int task = tid; task < B * 64; task += 256) {
    int img = task >> 6, j = task & 63;
    float a = b_sc1[j];
    const float* gr = g_g + img * D;
    for (int d = 0; d < D; d++) a = fmaf(gr[d], w_sc1[(size_t)d * 64 + j], a);
    s1[img][j] = fmaxf(a, 0.f);
  }
  __syncthreads();
  if (tid < B * 3) {
    int img = tid / 3, c = tid % 3;
    float a = b_sc2[c];
    for (int k = 0; k < 64; k++) a = fmaf(s1[img][k], w_sc2[k * 3 + c], a);
    lg[img][c] = a;
    g_skin_logits[img * 3 + c] = a;
  }
  __syncthreads();
  if (tid < B) {
    float l0 = lg[tid][0], l1 = lg[tid][1], l2 = lg[tid][2];
    float m = fmaxf(l0, fmaxf(l1, l2));
    float p0 = expf(l0 - m), p1 = expf(l1 - m), p2 = expf(l2 - m);
    float inv = 1.f / (p0 + p1 + p2);
    g_skin_probs[tid * 3 + 0] = p0 * inv;
    g_skin_probs[tid * 3 + 1] = p1 * inv;
    g_skin_probs[tid * 3 + 2] = p2 * inv;
  }
}

// ---------------- per-layer prep: zero counters ----------------
__global__ void prep_kernel(int zero_aux_total) {
  int i = threadIdx.x;
  if (i < E) g_counts[i] = 0;
  if (i < B * E) {
    g_aux_probs[i] = 0.f;
    g_aux_mask[i] = 0.f;
  }
  if (i == 0 && zero_aux_total) g_aux_total = 0.f;
}

// ---------------- router: logits -> softmax -> top2 buckets; also copies h -> hnxt ----------------
__global__ __launch_bounds__(256) void router_kernel(int flip,
                                                     const float* __restrict__ w_rimg_l,
                                                     const float* __restrict__ w_rskin_l) {
  const float* hcur = flip ? g_hB : g_hA;
  float* hnxt = flip ? g_hA : g_hB;
  int t = (int)((blockIdx.x * 256u + threadIdx.x) >> 5);
  int lane = threadIdx.x & 31;
  if (t >= NT) return;
  float acc[E];
#pragma unroll
  for (int e = 0; e < E; e++) acc[e] = 0.f;
  const float* hrow = hcur + (size_t)t * D;
  float* orow = hnxt + (size_t)t * D;
  for (int d = lane; d < D; d += 32) {
    float hv = hrow[d];
    orow[d] = hv;  // fused copy: hnxt starts as hcur, MoE accumulates into it
    const float* wr = w_rimg_l + (size_t)d * E;
#pragma unroll
    for (int e = 0; e < E; e++) acc[e] = fmaf(hv, wr[e], acc[e]);
  }
#pragma unroll
  for (int e = 0; e < E; e++)
#pragma unroll
    for (int off = 16; off > 0; off >>= 1) acc[e] += __shfl_xor_sync(0xffffffffu, acc[e], off);

  if (lane == 0) {
    int img = t >> 12;
    float p[E];
    float m = -1e30f;
#pragma unroll
    for (int e = 0; e < E; e++) {
      float s = acc[e];
#pragma unroll
      for (int k = 0; k < 3; k++) s = fmaf(g_skin_probs[img * 3 + k], w_rskin_l[k * E + e], s);
      p[e] = s;
      m = fmaxf(m, s);
    }
    float sum = 0.f;
#pragma unroll
    for (int e = 0; e < E; e++) {
      p[e] = expf(p[e] - m);
      sum += p[e];
    }
    float inv = 1.f / sum;
#pragma unroll
    for (int e = 0; e < E; e++) p[e] *= inv;
    // top-2, ties -> lowest index (matches lax.top_k)
    int i0 = 0;
#pragma unroll
    for (int e = 1; e < E; e++)
      if (p[e] > p[i0]) i0 = e;
    int i1 = (i0 == 0) ? 1 : 0;
#pragma unroll
    for (int e = 0; e < E; e++)
      if (e != i0 && p[e] > p[i1]) i1 = e;
    float denom = p[i0] + p[i1] + 1e-6f;
    float w0 = p[i0] / denom, w1 = p[i1] / denom;
    int pos0 = atomicAdd(&g_counts[i0], 1);
    g_btok[i0 * CAP + pos0] = t;
    g_bw[i0 * CAP + pos0] = w0;
    int pos1 = atomicAdd(&g_counts[i1], 1);
    g_btok[i1 * CAP + pos1] = t;
    g_bw[i1 * CAP + pos1] = w1;
#pragma unroll
    for (int e = 0; e < E; e++) atomicAdd(&g_aux_probs[img * E + e], p[e]);
    atomicAdd(&g_aux_mask[img * E + i0], 1.f);
    atomicAdd(&g_aux_mask[img * E + i1], 1.f);
  }
}

// ---------------- aux finalize (per layer): aux_total += E * sum(probs_mean * mask_mean) ----------------
__global__ void auxfin_kernel() {
  __shared__ float red[64];
  int i = threadIdx.x;
  float v = (g_aux_probs[i] * (1.f / (float)T)) * (g_aux_mask[i] * (1.f / (float)T)) * (float)E;
  red[i] = v;
  __syncthreads();
  for (int s = 32; s > 0; s >>= 1) {
    if (i < s) red[i] += red[i + s];
    __syncthreads();
  }
  if (i == 0) g_aux_total += red[0];
}

// ---------------- grouped MoE: per (expert, 64-token tile): relu(X@W1+b1)@W2+b2, scaled scatter-add ----------------
__global__ __launch_bounds__(256) void moe_kernel(int flip,
                                                  const float* __restrict__ ew1_l,
                                                  const float* __restrict__ eb1_l,
                                                  const float* __restrict__ ew2_l,
                                                  const float* __restrict__ eb2_l) {
  const float* hcur = flip ? g_hB : g_hA;
  float* hnxt = flip ? g_hA : g_hB;
  int e = blockIdx.y;
  int n_e = g_counts[e];
  int t0 = blockIdx.x * 64;
  if (t0 >= n_e) return;
  int mrows = min(64, n_e - t0);

  __shared__ float Xs[16][68];
  __shared__ float Ws[16][64];
  __shared__ float H1s[64][65];
  __shared__ int toks[64];
  __shared__ float tws[64];

  int tid = threadIdx.x;
  int tx = tid & 15, ty = tid >> 4;

  if (tid < 64) {
    int gi = t0 + tid;
    if (gi < n_e) {
      toks[tid] = g_btok[e * CAP + gi];
      tws[tid] = g_bw[e * CAP + gi];
    } else {
      toks[tid] = 0;
      tws[tid] = 0.f;
    }
  }
  __syncthreads();

  const float* w1e = ew1_l + (size_t)e * D * BNK;
  const float* w2e = ew2_l + (size_t)e * BNK * D;
  const float* b1e = eb1_l + (size_t)e * BNK;
  const float* b2e = eb2_l + (size_t)e * D;

  // ---- stage 1: H1 = relu(X(64x1024) @ W1(1024x64) + b1) ----
  float acc1[4][4];
#pragma unroll
  for (int i = 0; i < 4; i++)
#pragma unroll
    for (int j = 0; j < 4; j++) acc1[i][j] = 0.f;

  for (int k0 = 0; k0 < D; k0 += 16) {
    {
      int r = tid >> 2;
      int c = (tid & 3) * 4;
      const float* src = hcur + (size_t)toks[r] * D + k0 + c;
      bool ok = (r < mrows);
#pragma unroll
      for (int j = 0; j < 4; j++) Xs[c + j][r] = ok ? src[j] : 0.f;
    }
    {
      int kr0 = tid >> 6;  // 0..3
      int c = tid & 63;
#pragma unroll
      for (int j = 0; j < 4; j++) {
        int kr = kr0 + j * 4;
        Ws[kr][c] = w1e[(size_t)(k0 + kr) * BNK + c];
      }
    }
    __syncthreads();
#pragma unroll
    for (int kk = 0; kk < 16; kk++) {
      float a[4], b[4];
#pragma unroll
      for (int i = 0; i < 4; i++) a[i] = Xs[kk][ty + 16 * i];
#pragma unroll
      for (int j = 0; j < 4; j++) b[j] = Ws[kk][tx + 16 * j];
#pragma unroll
      for (int i = 0; i < 4; i++)
#pragma unroll
        for (int j = 0; j < 4; j++) acc1[i][j] = fmaf(a[i], b[j], acc1[i][j]);
    }
    __syncthreads();
  }
#pragma unroll
  for (int i = 0; i < 4; i++) {
#pragma unroll
    for (int j = 0; j < 4; j++) {
      int c = tx + 16 * j;
      H1s[ty + 16 * i][c] = fmaxf(acc1[i][j] + b1e[c], 0.f);
    }
  }
  __syncthreads();

  // ---- stage 2: OUT = H1(64x64) @ W2(64x1024) + b2, scale by token weight, scatter-add ----
  for (int c0 = 0; c0 < D; c0 += 64) {
    float acc2[4][4];
#pragma unroll
    for (int i = 0; i < 4; i++)
#pragma unroll
      for (int j = 0; j < 4; j++) acc2[i][j] = 0.f;
#pragma unroll 4
    for (int k = 0; k < BNK; k++) {
      float a[4], b[4];
#pragma unroll
      for (int i = 0; i < 4; i++) a[i] = H1s[ty + 16 * i][k];
#pragma unroll
      for (int j = 0; j < 4; j++) b[j] = __ldg(&w2e[(size_t)k * D + c0 + tx + 16 * j]);
#pragma unroll
      for (int i = 0; i < 4; i++)
#pragma unroll
        for (int j = 0; j < 4; j++) acc2[i][j] = fmaf(a[i], b[j], acc2[i][j]);
    }
#pragma unroll
    for (int i = 0; i < 4; i++) {
      int r = ty + 16 * i;
      if (r < mrows) {
        float w = tws[r];
        float* dst = hnxt + (size_t)toks[r] * D + c0;
#pragma unroll
        for (int j = 0; j < 4; j++) {
          int c = tx + 16 * j;
          atomicAdd(&dst[c], w * (acc2[i][j] + b2e[c0 + c]));
        }
      }
    }
  }
}

// ---------------- pooled = mean over T of final h (lives in g_hA after 4 layers) ----------------
__global__ void pooled_kernel(float* __restrict__ out) {
  int img = blockIdx.x;
  int d = blockIdx.y * 256 + threadIdx.x;
  const float* base = g_hA + (size_t)img * T * D + d;
  float s0 = 0.f, s1 = 0.f, s2 = 0.f, s3 = 0.f;
  for (int t = 0; t < T; t += 4) {
    s0 += base[(size_t)t * D];
    s1 += base[(size_t)(t + 1) * D];
    s2 += base[(size_t)(t + 2) * D];
    s3 += base[(size_t)(t + 3) * D];
  }
  out[img * D + d] = (s0 + s1 + s2 + s3) * (1.f / (float)T);
}

// ---------------- vision_proj = pooled @ w_out + b_out ----------------
__global__ __launch_bounds__(256) void vproj_kernel(const float* __restrict__ w_out,
                                                    const float* __restrict__ b_out,
                                                    float* __restrict__ out) {
  __shared__ float ps[B * D];  // 32 KB
  for (int i = threadIdx.x; i < B * D; i += 256) ps[i] = out[i];
  __syncthreads();
  int o = blockIdx.x * 256 + threadIdx.x;
  float acc[B];
#pragma unroll
  for (int i = 0; i < B; i++) acc[i] = 0.f;
  for (int d = 0; d < D; d++) {
    float wv = w_out[(size_t)d * OUTD + o];
#pragma unroll
    for (int i = 0; i < B; i++) acc[i] = fmaf(ps[i * D + d], wv, acc[i]);
  }
  float bo = b_out[o];
  float* vp = out + B * D;
#pragma unroll
  for (int i = 0; i < B; i++) vp[(size_t)i * OUTD + o] = acc[i] + bo;
}

// ---------------- pack tail outputs: aux scalar + skin logits ----------------
__global__ void pack_kernel(float* __restrict__ out, int out_size) {
  const int base = B * D + B * OUTD;  // 40960
  int i = threadIdx.x;
  if (i == 0) out[base] = g_aux_total;
  if (i < B * 3) out[base + 1 + i] = g_skin_logits[i];
  for (int j = base + 1 + B * 3 + i; j < out_size; j += 256) out[j] = 0.f;
}

// ---------------- launch ----------------
extern "C" void kernel_launch(void* const* d_in, const int* in_sizes, int n_in,
                              void* d_out, int out_size) {
  const float* pixel_values = (const float*)d_in[0];
  // d_in[1] = image_grid_thw (unused: uniform 1x64x64 grids)
  const float* w_in    = (const float*)d_in[2];
  const float* w_sc1   = (const float*)d_in[3];
  const float* b_sc1   = (const float*)d_in[4];
  const float* w_sc2   = (const float*)d_in[5];
  const float* b_sc2   = (const float*)d_in[6];
  const float* w_rimg  = (const float*)d_in[7];
  const float* w_rskin = (const float*)d_in[8];
  const float* ew1     = (const float*)d_in[9];
  const float* eb1     = (const float*)d_in[10];
  const float* ew2     = (const float*)d_in[11];
  const float* eb2     = (const float*)d_in[12];
  const float* w_out   = (const float*)d_in[13];
  const float* b_out   = (const float*)d_in[14];
  float* out = (float*)d_out;

  inproj_kernel<<<dim3(D / 128, NT / 128), 256>>>(pixel_values, w_in);
  gmean_kernel<<<dim3(B, D / 256), 256>>>();
  skin_kernel<<<1, 256>>>(w_sc1, b_sc1, w_sc2, b_sc2);

  for (int l = 0; l < L; l++) {
    int flip = l & 1;
    prep_kernel<<<1, 64>>>(l == 0 ? 1 : 0);
    router_kernel<<<NT / 8, 256>>>(flip, w_rimg + (size_t)l * D * E, w_rskin + (size_t)l * 3 * E);
    auxfin_kernel<<<1, 64>>>();
    moe_kernel<<<dim3(NT / 64, E), 256>>>(flip,
                                          ew1 + (size_t)l * E * D * BNK,
                                          eb1 + (size_t)l * E * BNK,
                                          ew2 + (size_t)l * E * BNK * D,
                                          eb2 + (size_t)l * E * D);
  }

  pooled_kernel<<<dim3(B, D / 256), 256>>>(out);
  vproj_kernel<<<OUTD / 256, 256>>>(w_out, b_out, out);
  pack_kernel<<<1, 256>>>(out, out_size);
}

// round 3
// speedup vs baseline: 1.4697x; 1.4697x over previous
#include <cuda_runtime.h>
#include <cstdint>
#include <cstddef>

// ---------------- problem constants ----------------
namespace {
constexpr int B    = 8;
constexpr int T    = 4096;
constexpr int NT   = B * T;        // 32768 tokens
constexpr int DIN  = 1176;
constexpr int D    = 1024;
constexpr int E    = 8;
constexpr int BNK  = 64;           // bottleneck
constexpr int L    = 4;
constexpr int OUTD = 4096;
constexpr int CAP  = 32768;        // max tokens per expert bucket
}

// ---------------- device scratch (no runtime allocs allowed) ----------------
__device__ float g_hA[(size_t)NT * D];
__device__ float g_hB[(size_t)NT * D];
__device__ float g_g[B * D];
__device__ float g_skin_probs[B * 3];
__device__ float g_skin_logits[B * 3];
__device__ int   g_counts[E];
__device__ int   g_btok[E * CAP];
__device__ float g_bw[E * CAP];
__device__ float g_aux_probs[B * E];
__device__ float g_aux_mask[B * E];
__device__ float g_aux_total;

// ---------------- tf32 helpers (3xTF32 split precision) ----------------
__device__ __forceinline__ void splitf(float x, uint32_t& h, uint32_t& l) {
  asm("cvt.rna.tf32.f32 %0, %1;" : "=r"(h) : "f"(x));
  float r = x - __uint_as_float(h);
  asm("cvt.rna.tf32.f32 %0, %1;" : "=r"(l) : "f"(r));
}

__device__ __forceinline__ void mma8(float* c, const uint32_t* a, const uint32_t* b) {
  asm volatile(
      "mma.sync.aligned.m16n8k8.row.col.f32.tf32.tf32.f32 "
      "{%0,%1,%2,%3}, {%4,%5,%6,%7}, {%8,%9}, {%0,%1,%2,%3};"
      : "+f"(c[0]), "+f"(c[1]), "+f"(c[2]), "+f"(c[3])
      : "r"(a[0]), "r"(a[1]), "r"(a[2]), "r"(a[3]), "r"(b[0]), "r"(b[1]));
}

// ---------------- in_proj GEMM (tensor core, 3xTF32): g_hA = X @ W ----------------
// 128x128 tile, BK=8, 256 threads, warp grid 2(m) x 4(n), warp tile 64x32.
__global__ __launch_bounds__(256) void inproj_mma(const float* __restrict__ X,
                                                  const float* __restrict__ W) {
  __shared__ float As[128][12];   // stride 12: frag banks (12m+k)%32 conflict-free
  __shared__ float Bs[8][136];    // stride 136: (8k+n)%32 conflict-free
  int tid = threadIdx.x, lane = tid & 31, wid = tid >> 5;
  int wm = (wid & 1) * 64, wn = (wid >> 1) * 32;
  int m0 = blockIdx.y * 128, n0 = blockIdx.x * 128;

  float acc[4][4][4];
#pragma unroll
  for (int i = 0; i < 4; i++)
#pragma unroll
    for (int j = 0; j < 4; j++)
#pragma unroll
      for (int q = 0; q < 4; q++) acc[i][j][q] = 0.f;

  int la_m = tid >> 1, la_k = (tid & 1) * 4;
  int lb_k = tid >> 5, lb_n = (tid & 31) * 4;
  const float* xptr = X + (size_t)(m0 + la_m) * DIN + la_k;
  const float* wptr = W + (size_t)lb_k * D + n0 + lb_n;

  float4 pa = *(const float4*)(xptr);
  float4 pb = *(const float4*)(wptr);

  for (int k0 = 0; k0 < DIN; k0 += 8) {
    __syncthreads();
    *(float4*)&As[la_m][la_k] = pa;
    *(float4*)&Bs[lb_k][lb_n] = pb;
    __syncthreads();
    if (k0 + 8 < DIN) {
      pa = *(const float4*)(xptr + k0 + 8);
      pb = *(const float4*)(wptr + (size_t)(k0 + 8) * D);
    }
    int ar = lane >> 2, ac = lane & 3;
    uint32_t ah[4][4], al[4][4];
#pragma unroll
    for (int i = 0; i < 4; i++) {
      int r0 = wm + i * 16 + ar;
      splitf(As[r0][ac],         ah[i][0], al[i][0]);
      splitf(As[r0 + 8][ac],     ah[i][1], al[i][1]);
      splitf(As[r0][ac + 4],     ah[i][2], al[i][2]);
      splitf(As[r0 + 8][ac + 4], ah[i][3], al[i][3]);
    }
#pragma unroll
    for (int j = 0; j < 4; j++) {
      int cb = wn + j * 8 + ar;
      uint32_t bh[2], bl[2];
      splitf(Bs[ac][cb],     bh[0], bl[0]);
      splitf(Bs[ac + 4][cb], bh[1], bl[1]);
#pragma unroll
      for (int i = 0; i < 4; i++) {
        mma8(acc[i][j], al[i], bh);
        mma8(acc[i][j], ah[i], bl);
        mma8(acc[i][j], ah[i], bh);
      }
    }
  }
  int ar = lane >> 2, ac2 = (lane & 3) * 2;
#pragma unroll
  for (int i = 0; i < 4; i++) {
    int r = m0 + wm + i * 16 + ar;
#pragma unroll
    for (int j = 0; j < 4; j++) {
      int c = n0 + wn + j * 8 + ac2;
      *(float2*)&g_hA[(size_t)r * D + c]       = make_float2(acc[i][j][0], acc[i][j][1]);
      *(float2*)&g_hA[(size_t)(r + 8) * D + c] = make_float2(acc[i][j][2], acc[i][j][3]);
    }
  }
}

// ---------------- per-image mean of g_hA -> g_g ----------------
__global__ void gmean_kernel() {
  int img = blockIdx.x;
  int d = blockIdx.y * 256 + threadIdx.x;
  const float* base = g_hA + (size_t)img * T * D + d;
  float s0 = 0.f, s1 = 0.f, s2 = 0.f, s3 = 0.f;
  for (int t = 0; t < T; t += 4) {
    s0 += base[(size_t)t * D];
    s1 += base[(size_t)(t + 1) * D];
    s2 += base[(size_t)(t + 2) * D];
    s3 += base[(size_t)(t + 3) * D];
  }
  g_g[img * D + d] = (s0 + s1 + s2 + s3) * (1.f / (float)T);
}

// ---------------- skin classifier ----------------
__global__ __launch_bounds__(256) void skin_kernel(const float* __restrict__ w_sc1,
                                                   const float* __restrict__ b_sc1,
                                                   const float* __restrict__ w_sc2,
                                                   const float* __restrict__ b_sc2) {
  __shared__ float s1[B][64];
  __shared__ float lg[B][3];
  int tid = threadIdx.x;
  for (int task = tid; task < B * 64; task += 256) {
    int img = task >> 6, j = task & 63;
    float a = b_sc1[j];
    const float* gr = g_g + img * D;
    for (int d = 0; d < D; d++) a = fmaf(gr[d], w_sc1[(size_t)d * 64 + j], a);
    s1[img][j] = fmaxf(a, 0.f);
  }
  __syncthreads();
  if (tid < B * 3) {
    int img = tid / 3, c = tid % 3;
    float a = b_sc2[c];
    for (int k = 0; k < 64; k++) a = fmaf(s1[img][k], w_sc2[k * 3 + c], a);
    lg[img][c] = a;
    g_skin_logits[img * 3 + c] = a;
  }
  __syncthreads();
  if (tid < B) {
    float l0 = lg[tid][0], l1 = lg[tid][1], l2 = lg[tid][2];
    float m = fmaxf(l0, fmaxf(l1, l2));
    float p0 = expf(l0 - m), p1 = expf(l1 - m), p2 = expf(l2 - m);
    float inv = 1.f / (p0 + p1 + p2);
    g_skin_probs[tid * 3 + 0] = p0 * inv;
    g_skin_probs[tid * 3 + 1] = p1 * inv;
    g_skin_probs[tid * 3 + 2] = p2 * inv;
  }
}

// ---------------- per-layer prep ----------------
__global__ void prep_kernel(int zero_aux_total) {
  int i = threadIdx.x;
  if (i < E) g_counts[i] = 0;
  if (i < B * E) {
    g_aux_probs[i] = 0.f;
    g_aux_mask[i] = 0.f;
  }
  if (i == 0 && zero_aux_total) g_aux_total = 0.f;
}

// ---------------- router (unchanged, fp32; also h -> hnxt copy) ----------------
__global__ __launch_bounds__(256) void router_kernel(int flip,
                                                     const float* __restrict__ w_rimg_l,
                                                     const float* __restrict__ w_rskin_l) {
  const float* hcur = flip ? g_hB : g_hA;
  float* hnxt = flip ? g_hA : g_hB;
  int t = (int)((blockIdx.x * 256u + threadIdx.x) >> 5);
  int lane = threadIdx.x & 31;
  if (t >= NT) return;
  float acc[E];
#pragma unroll
  for (int e = 0; e < E; e++) acc[e] = 0.f;
  const float* hrow = hcur + (size_t)t * D;
  float* orow = hnxt + (size_t)t * D;
  for (int d = lane; d < D; d += 32) {
    float hv = hrow[d];
    orow[d] = hv;
    const float* wr = w_rimg_l + (size_t)d * E;
#pragma unroll
    for (int e = 0; e < E; e++) acc[e] = fmaf(hv, wr[e], acc[e]);
  }
#pragma unroll
  for (int e = 0; e < E; e++)
#pragma unroll
    for (int off = 16; off > 0; off >>= 1) acc[e] += __shfl_xor_sync(0xffffffffu, acc[e], off);

  if (lane == 0) {
    int img = t >> 12;
    float p[E];
    float m = -1e30f;
#pragma unroll
    for (int e = 0; e < E; e++) {
      float s = acc[e];
#pragma unroll
      for (int k = 0; k < 3; k++) s = fmaf(g_skin_probs[img * 3 + k], w_rskin_l[k * E + e], s);
      p[e] = s;
      m = fmaxf(m, s);
    }
    float sum = 0.f;
#pragma unroll
    for (int e = 0; e < E; e++) {
      p[e] = expf(p[e] - m);
      sum += p[e];
    }
    float inv = 1.f / sum;
#pragma unroll
    for (int e = 0; e < E; e++) p[e] *= inv;
    int i0 = 0;
#pragma unroll
    for (int e = 1; e < E; e++)
      if (p[e] > p[i0]) i0 = e;
    int i1 = (i0 == 0) ? 1 : 0;
#pragma unroll
    for (int e = 0; e < E; e++)
      if (e != i0 && p[e] > p[i1]) i1 = e;
    float denom = p[i0] + p[i1] + 1e-6f;
    float w0 = p[i0] / denom, w1 = p[i1] / denom;
    int pos0 = atomicAdd(&g_counts[i0], 1);
    g_btok[i0 * CAP + pos0] = t;
    g_bw[i0 * CAP + pos0] = w0;
    int pos1 = atomicAdd(&g_counts[i1], 1);
    g_btok[i1 * CAP + pos1] = t;
    g_bw[i1 * CAP + pos1] = w1;
#pragma unroll
    for (int e = 0; e < E; e++) atomicAdd(&g_aux_probs[img * E + e], p[e]);
    atomicAdd(&g_aux_mask[img * E + i0], 1.f);
    atomicAdd(&g_aux_mask[img * E + i1], 1.f);
  }
}

// ---------------- aux finalize ----------------
__global__ void auxfin_kernel() {
  __shared__ float red[64];
  int i = threadIdx.x;
  float v = (g_aux_probs[i] * (1.f / (float)T)) * (g_aux_mask[i] * (1.f / (float)T)) * (float)E;
  red[i] = v;
  __syncthreads();
  for (int s = 32; s > 0; s >>= 1) {
    if (i < s) red[i] += red[i + s];
    __syncthreads();
  }
  if (i == 0) g_aux_total += red[0];
}

// ---------------- grouped MoE (tensor core, 3xTF32) ----------------
// per (expert, 64-token tile): H1 = relu(X@W1+b1); OUT = H1@W2+b2 scaled scatter-add.
// 256 threads, warp grid 4(m) x 2(n), warp tile 16x32.
__global__ __launch_bounds__(256) void moe_mma(int flip,
                                               const float* __restrict__ ew1_l,
                                               const float* __restrict__ eb1_l,
                                               const float* __restrict__ ew2_l,
                                               const float* __restrict__ eb2_l) {
  const float* hcur = flip ? g_hB : g_hA;
  float* hnxt = flip ? g_hA : g_hB;
  int e = blockIdx.y;
  int n_e = g_counts[e];
  int t0 = blockIdx.x * 64;
  if (t0 >= n_e) return;
  int mrows = min(64, n_e - t0);

  // sAB: stage1 { As[64][36] @0 (2304), B1s[32][72] @2304 (2304) } / stage2 { W2s[64][72] @0 (4608) }
  __shared__ float sAB[4608];
  __shared__ float H1s[64][68];   // stride 68: (4m+k)%32 conflict-free
  __shared__ int   toks[64];
  __shared__ float tws[64];
  float* As  = sAB;         // stride 36
  float* B1s = sAB + 2304;  // stride 72
  float* W2s = sAB;         // stride 72

  int tid = threadIdx.x, lane = tid & 31, wid = tid >> 5;
  int wm = (wid & 3) * 16, wn = (wid >> 2) * 32;
  int ar = lane >> 2, ac = lane & 3;

  if (tid < 64) {
    int gi = t0 + tid;
    if (gi < n_e) {
      toks[tid] = g_btok[e * CAP + gi];
      tws[tid]  = g_bw[e * CAP + gi];
    } else {
      toks[tid] = 0;
      tws[tid]  = 0.f;
    }
  }
  __syncthreads();

  const float* w1e = ew1_l + (size_t)e * D * BNK;
  const float* w2e = ew2_l + (size_t)e * BNK * D;
  const float* b1e = eb1_l + (size_t)e * BNK;
  const float* b2e = eb2_l + (size_t)e * D;

  // ---- stage 1: H1 = relu(X(64x1024) @ W1(1024x64) + b1) ----
  float acc1[4][4];
#pragma unroll
  for (int j = 0; j < 4; j++)
#pragma unroll
    for (int q = 0; q < 4; q++) acc1[j][q] = 0.f;

  int a_m = tid >> 2, a_k = (tid & 3) * 8;  // 64 rows x 4 threads, 8 floats each
  int b_k = tid >> 3, b_n = (tid & 7) * 8;  // 32 rows x 8 threads, 8 floats each
  const float* a_src = hcur + (size_t)toks[a_m] * D + a_k;

  float4 pa0 = *(const float4*)(a_src);
  float4 pa1 = *(const float4*)(a_src + 4);
  float4 pb0 = *(const float4*)(w1e + (size_t)b_k * BNK + b_n);
  float4 pb1 = *(const float4*)(w1e + (size_t)b_k * BNK + b_n + 4);

  for (int k0 = 0; k0 < D; k0 += 32) {
    __syncthreads();
    *(float4*)&As[a_m * 36 + a_k]     = pa0;
    *(float4*)&As[a_m * 36 + a_k + 4] = pa1;
    *(float4*)&B1s[b_k * 72 + b_n]     = pb0;
    *(float4*)&B1s[b_k * 72 + b_n + 4] = pb1;
    __syncthreads();
    if (k0 + 32 < D) {
      pa0 = *(const float4*)(a_src + k0 + 32);
      pa1 = *(const float4*)(a_src + k0 + 36);
      pb0 = *(const float4*)(w1e + (size_t)(k0 + 32 + b_k) * BNK + b_n);
      pb1 = *(const float4*)(w1e + (size_t)(k0 + 32 + b_k) * BNK + b_n + 4);
    }
#pragma unroll
    for (int ks = 0; ks < 4; ks++) {
      int kb = ks * 8;
      uint32_t ah[4], al[4];
      int r0 = wm + ar;
      splitf(As[r0 * 36 + kb + ac],           ah[0], al[0]);
      splitf(As[(r0 + 8) * 36 + kb + ac],     ah[1], al[1]);
      splitf(As[r0 * 36 + kb + ac + 4],       ah[2], al[2]);
      splitf(As[(r0 + 8) * 36 + kb + ac + 4], ah[3], al[3]);
#pragma unroll
      for (int j = 0; j < 4; j++) {
        int cb = wn + j * 8 + ar;
        uint32_t bh[2], bl[2];
        splitf(B1s[(kb + ac) * 72 + cb],     bh[0], bl[0]);
        splitf(B1s[(kb + ac + 4) * 72 + cb], bh[1], bl[1]);
        mma8(acc1[j], al, bh);
        mma8(acc1[j], ah, bl);
        mma8(acc1[j], ah, bh);
      }
    }
  }
  __syncthreads();
  {
    int r = wm + ar;
    int c2 = (lane & 3) * 2;
#pragma unroll
    for (int j = 0; j < 4; j++) {
      int c = wn + j * 8 + c2;
      H1s[r][c]         = fmaxf(acc1[j][0] + b1e[c], 0.f);
      H1s[r][c + 1]     = fmaxf(acc1[j][1] + b1e[c + 1], 0.f);
      H1s[r + 8][c]     = fmaxf(acc1[j][2] + b1e[c], 0.f);
      H1s[r + 8][c + 1] = fmaxf(acc1[j][3] + b1e[c + 1], 0.f);
    }
  }

  // ---- stage 2: OUT = H1(64x64) @ W2(64x1024) + b2, weighted scatter-add ----
  int w_k = tid >> 2, w_n = (tid & 3) * 16;  // 64 rows x 4 threads, 16 floats each
  float4 pw[4];
#pragma unroll
  for (int q = 0; q < 4; q++)
    pw[q] = *(const float4*)(w2e + (size_t)w_k * D + w_n + 4 * q);

  for (int c0 = 0; c0 < D; c0 += 64) {
    __syncthreads();
#pragma unroll
    for (int q = 0; q < 4; q++) *(float4*)&W2s[w_k * 72 + w_n + 4 * q] = pw[q];
    __syncthreads();
    if (c0 + 64 < D) {
#pragma unroll
      for (int q = 0; q < 4; q++)
        pw[q] = *(const float4*)(w2e + (size_t)w_k * D + c0 + 64 + w_n + 4 * q);
    }
    float acc2[4][4];
#pragma unroll
    for (int j = 0; j < 4; j++)
#pragma unroll
      for (int q = 0; q < 4; q++) acc2[j][q] = 0.f;
#pragma unroll
    for (int ks = 0; ks < 8; ks++) {
      int kb = ks * 8;
      uint32_t ah[4], al[4];
      int r0 = wm + ar;
      splitf(H1s[r0][kb + ac],         ah[0], al[0]);
      splitf(H1s[r0 + 8][kb + ac],     ah[1], al[1]);
      splitf(H1s[r0][kb + ac + 4],     ah[2], al[2]);
      splitf(H1s[r0 + 8][kb + ac + 4], ah[3], al[3]);
#pragma unroll
      for (int j = 0; j < 4; j++) {
        int cb = wn + j * 8 + ar;
        uint32_t bh[2], bl[2];
        splitf(W2s[(kb + ac) * 72 + cb],     bh[0], bl[0]);
        splitf(W2s[(kb + ac + 4) * 72 + cb], bh[1], bl[1]);
        mma8(acc2[j], al, bh);
        mma8(acc2[j], ah, bl);
        mma8(acc2[j], ah, bh);
      }
    }
    // epilogue: bias + token weight + atomic scatter
    int r = wm + ar;
    int c2 = (lane & 3) * 2;
    if (r < mrows) {
      float w = tws[r];
      float* dst = hnxt + (size_t)toks[r] * D + c0;
#pragma unroll
      for (int j = 0; j < 4; j++) {
        int c = wn + j * 8 + c2;
        atomicAdd(&dst[c],     w * (acc2[j][0] + b2e[c0 + c]));
        atomicAdd(&dst[c + 1], w * (acc2[j][1] + b2e[c0 + c + 1]));
      }
    }
    if (r + 8 < mrows) {
      float w = tws[r + 8];
      float* dst = hnxt + (size_t)toks[r + 8] * D + c0;
#pragma unroll
      for (int j = 0; j < 4; j++) {
        int c = wn + j * 8 + c2;
        atomicAdd(&dst[c],     w * (acc2[j][2] + b2e[c0 + c]));
        atomicAdd(&dst[c + 1], w * (acc2[j][3] + b2e[c0 + c + 1]));
      }
    }
  }
}

// ---------------- pooled = mean over T of final h (in g_hA after 4 layers) ----------------
__global__ void pooled_kernel(float* __restrict__ out) {
  int img = blockIdx.x;
  int d = blockIdx.y * 256 + threadIdx.x;
  const float* base = g_hA + (size_t)img * T * D + d;
  float s0 = 0.f, s1 = 0.f, s2 = 0.f, s3 = 0.f;
  for (int t = 0; t < T; t += 4) {
    s0 += base[(size_t)t * D];
    s1 += base[(size_t)(t + 1) * D];
    s2 += base[(size_t)(t + 2) * D];
    s3 += base[(size_t)(t + 3) * D];
  }
  out[img * D + d] = (s0 + s1 + s2 + s3) * (1.f / (float)T);
}

// ---------------- vision_proj = pooled @ w_out + b_out ----------------
__global__ __launch_bounds__(256) void vproj_kernel(const float* __restrict__ w_out,
                                                    const float* __restrict__ b_out,
                                                    float* __restrict__ out) {
  __shared__ float ps[B * D];
  for (int i = threadIdx.x; i < B * D; i += 256) ps[i] = out[i];
  __syncthreads();
  int o = blockIdx.x * 256 + threadIdx.x;
  float acc[B];
#pragma unroll
  for (int i = 0; i < B; i++) acc[i] = 0.f;
  for (int d = 0; d < D; d++) {
    float wv = w_out[(size_t)d * OUTD + o];
#pragma unroll
    for (int i = 0; i < B; i++) acc[i] = fmaf(ps[i * D + d], wv, acc[i]);
  }
  float bo = b_out[o];
  float* vp = out + B * D;
#pragma unroll
  for (int i = 0; i < B; i++) vp[(size_t)i * OUTD + o] = acc[i] + bo;
}

// ---------------- pack tail outputs ----------------
__global__ void pack_kernel(float* __restrict__ out, int out_size) {
  const int base = B * D + B * OUTD;
  int i = threadIdx.x;
  if (i == 0) out[base] = g_aux_total;
  if (i < B * 3) out[base + 1 + i] = g_skin_logits[i];
  for (int j = base + 1 + B * 3 + i; j < out_size; j += 256) out[j] = 0.f;
}

// ---------------- launch ----------------
extern "C" void kernel_launch(void* const* d_in, const int* in_sizes, int n_in,
                              void* d_out, int out_size) {
  const float* pixel_values = (const float*)d_in[0];
  const float* w_in    = (const float*)d_in[2];
  const float* w_sc1   = (const float*)d_in[3];
  const float* b_sc1   = (const float*)d_in[4];
  const float* w_sc2   = (const float*)d_in[5];
  const float* b_sc2   = (const float*)d_in[6];
  const float* w_rimg  = (const float*)d_in[7];
  const float* w_rskin = (const float*)d_in[8];
  const float* ew1     = (const float*)d_in[9];
  const float* eb1     = (const float*)d_in[10];
  const float* ew2     = (const float*)d_in[11];
  const float* eb2     = (const float*)d_in[12];
  const float* w_out   = (const float*)d_in[13];
  const float* b_out   = (const float*)d_in[14];
  float* out = (float*)d_out;

  inproj_mma<<<dim3(D / 128, NT / 128), 256>>>(pixel_values, w_in);
  gmean_kernel<<<dim3(B, D / 256), 256>>>();
  skin_kernel<<<1, 256>>>(w_sc1, b_sc1, w_sc2, b_sc2);

  for (int l = 0; l < L; l++) {
    int flip = l & 1;
    prep_kernel<<<1, 64>>>(l == 0 ? 1 : 0);
    router_kernel<<<NT / 8, 256>>>(flip, w_rimg + (size_t)l * D * E, w_rskin + (size_t)l * 3 * E);
    auxfin_kernel<<<1, 64>>>();
    moe_mma<<<dim3(NT / 64, E), 256>>>(flip,
                                       ew1 + (size_t)l * E * D * BNK,
                                       eb1 + (size_t)l * E * BNK,
                                       ew2 + (size_t)l * E * BNK * D,
                                       eb2 + (size_t)l * E * D);
  }

  pooled_kernel<<<dim3(B, D / 256), 256>>>(out);
  vproj_kernel<<<OUTD / 256, 256>>>(w_out, b_out, out);
  pack_kernel<<<1, 256>>>(out, out_size);
}